// round 4
// baseline (speedup 1.0000x reference)
#include <cuda_runtime.h>
#include <cuda_fp16.h>
#include <cstdint>
#include <cstddef>

#define B_SZ    256
#define C_SZ    10
#define N_CAP   1152
#define DIN     8
#define U_SZ    16
#define B_CHUNK 64
#define NQUAD   (N_CAP / 4)       // 288

// 23.6 MB fp16 scratch for one chunk of u_hat, layout [b][c][p][n] (p = u-pair).
__device__ unsigned int g_uhat_h[(size_t)B_CHUNK * C_SZ * 8 * N_CAP];

#define FFMA2(d, a, bb, cc) \
    asm("fma.rn.f32x2 %0, %1, %2, %3;" : "=l"(d) : "l"(a), "l"(bb), "l"(cc))
#define DUP2(d, s) \
    asm("mov.b64 %0, {%1, %1};" : "=l"(d) : "r"(s))

// ---------------------------------------------------------------------------
// K1: u_hat[b,c,n,u] = sum_i x[b,n,i] * W[c,n,i,u]  -> fp16, [b][c][p][n].
// Grid (36, 10, B_CHUNK/16). 256 thr = 2 b-halves x 32 n x 4 u-quads.
// W slice (8i x 4u) in registers as 16 f32x2; x staged in smem (12-word rows,
// conflict-free LDS.128); per b-step: 2 LDS.128 + 8 dup + 16 FFMA2 + 2 STG.32.
// ---------------------------------------------------------------------------
__global__ __launch_bounds__(256) void k1_uhat(const float* __restrict__ x,
                                               const float* __restrict__ W)
{
    __shared__ float xs[16 * 32 * 12];   // 24KB

    const int n0 = blockIdx.x * 32;
    const int c  = blockIdx.y;
    const int b0 = blockIdx.z * 16;      // local-in-chunk

    for (int t = threadIdx.x; t < 512; t += 256) {
        const int b = t >> 5, n = t & 31;
        const float4* g = (const float4*)(x + ((size_t)(b0 + b) * N_CAP + (n0 + n)) * DIN);
        float4 v0 = g[0], v1 = g[1];
        float* d = xs + (b * 32 + n) * 12;
        *(float4*)(d)     = v0;
        *(float4*)(d + 4) = v1;
    }

    const int uq = threadIdx.x & 3;
    const int nl = (threadIdx.x >> 2) & 31;
    const int bl = threadIdx.x >> 7;     // 0..1
    const int n  = n0 + nl;

    unsigned long long wr[16];
    {
        const ulonglong2* Wp = (const ulonglong2*)(W + ((size_t)c * N_CAP + n) * 128);
        #pragma unroll
        for (int i = 0; i < 8; ++i) {
            ulonglong2 w = Wp[i * 4 + uq];
            wr[2 * i]     = w.x;
            wr[2 * i + 1] = w.y;
        }
    }
    __syncthreads();

    // store base: [b][c][p0=2uq][n]
    unsigned int* op = g_uhat_h +
        (((size_t)(b0 + bl * 8) * C_SZ + c) * 8 + 2 * uq) * N_CAP + n;

    #pragma unroll 4
    for (int s = 0; s < 8; ++s) {
        const int b = bl * 8 + s;
        const float* xp = xs + (b * 32 + nl) * 12;
        float4 xa = *(const float4*)(xp);
        float4 xb = *(const float4*)(xp + 4);

        unsigned long long x0, x1, x2, x3, x4, x5, x6, x7;
        DUP2(x0, __float_as_uint(xa.x));  DUP2(x1, __float_as_uint(xa.y));
        DUP2(x2, __float_as_uint(xa.z));  DUP2(x3, __float_as_uint(xa.w));
        DUP2(x4, __float_as_uint(xb.x));  DUP2(x5, __float_as_uint(xb.y));
        DUP2(x6, __float_as_uint(xb.z));  DUP2(x7, __float_as_uint(xb.w));

        unsigned long long a0 = 0ull, a1 = 0ull;
        FFMA2(a0, wr[0],  x0, a0);  FFMA2(a1, wr[1],  x0, a1);
        FFMA2(a0, wr[2],  x1, a0);  FFMA2(a1, wr[3],  x1, a1);
        FFMA2(a0, wr[4],  x2, a0);  FFMA2(a1, wr[5],  x2, a1);
        FFMA2(a0, wr[6],  x3, a0);  FFMA2(a1, wr[7],  x3, a1);
        FFMA2(a0, wr[8],  x4, a0);  FFMA2(a1, wr[9],  x4, a1);
        FFMA2(a0, wr[10], x5, a0);  FFMA2(a1, wr[11], x5, a1);
        FFMA2(a0, wr[12], x6, a0);  FFMA2(a1, wr[13], x6, a1);
        FFMA2(a0, wr[14], x7, a0);  FFMA2(a1, wr[15], x7, a1);

        unsigned int l0, h0, l1, h1;
        asm("mov.b64 {%0, %1}, %2;" : "=r"(l0), "=r"(h0) : "l"(a0));
        asm("mov.b64 {%0, %1}, %2;" : "=r"(l1), "=r"(h1) : "l"(a1));
        __half2 p0 = __floats2half2_rn(__uint_as_float(l0), __uint_as_float(h0));
        __half2 p1 = __floats2half2_rn(__uint_as_float(l1), __uint_as_float(h1));
        op[0]     = *(unsigned int*)&p0;         // pair 2uq
        op[N_CAP] = *(unsigned int*)&p1;         // pair 2uq+1
        op += (size_t)C_SZ * 8 * N_CAP;
    }
}

// ---------------------------------------------------------------------------
__device__ __forceinline__ float blockReduceSum(float v, float* scratch)
{
    #pragma unroll
    for (int o = 16; o > 0; o >>= 1) v += __shfl_xor_sync(0xffffffffu, v, o);
    if ((threadIdx.x & 31) == 0) scratch[threadIdx.x >> 5] = v;
    __syncthreads();
    float r = 0.f;
    #pragma unroll
    for (int i = 0; i < 8; ++i) r += scratch[i];
    __syncthreads();
    return r;
}

// ---------------------------------------------------------------------------
// K2: routing per (b,c). Grid (C, B_CHUNK), 256 thr, 37.5KB smem (5 CTA/SM).
// prologue: warp p streams its u-pair row global->smem, fused uniform-s0.
// pass(w): per n-quad, dot = u.w -> e = exp(dot); fused s[u] += e*u[n][u]
//          into 16 per-thread regs; second LDS sweep re-reads the quad.
// No b_log (logit linearity: b2 = u.(v0+v1)); no c_arr; no separate s-scans.
// ---------------------------------------------------------------------------
__global__ __launch_bounds__(256, 5) void k2_route(float* __restrict__ outp)
{
    extern __shared__ float sm[];
    unsigned int* uh = (unsigned int*)sm;     // 8 x 1152 half2-words (36.9KB)
    float* red  = sm + 8 * N_CAP;             // 128 (8 warps x 16 u)
    float* w_s  = red + 128;                  // 16 (pass weight vector)
    float* red2 = w_s + 16;                   // 8

    const int tid = threadIdx.x;
    const int c   = blockIdx.x;
    const int b   = blockIdx.y;               // local-in-chunk
    const int p   = tid >> 5;
    const int g   = tid & 31;

    // ---- prologue: load row p, store to smem, accumulate uniform s0 ----
    {
        const uint4* src = (const uint4*)(g_uhat_h +
                            (((size_t)b * C_SZ + c) * 8 + p) * N_CAP);
        unsigned int* uhp = uh + p * N_CAP;
        float sx = 0.f, sy = 0.f;
        #pragma unroll
        for (int k = 0; k < 9; ++k) {
            uint4 v = src[k * 32 + g];
            *(uint4*)(uhp + k * 128 + 4 * g) = v;
            float2 a0 = __half22float2(*(__half2*)&v.x);
            float2 a1 = __half22float2(*(__half2*)&v.y);
            float2 a2 = __half22float2(*(__half2*)&v.z);
            float2 a3 = __half22float2(*(__half2*)&v.w);
            sx += (a0.x + a1.x) + (a2.x + a3.x);
            sy += (a0.y + a1.y) + (a2.y + a3.y);
        }
        #pragma unroll
        for (int o = 16; o > 0; o >>= 1) {
            sx += __shfl_xor_sync(0xffffffffu, sx, o);
            sy += __shfl_xor_sync(0xffffffffu, sy, o);
        }
        if (g == 0) { red[2 * p] = sx; red[2 * p + 1] = sy; }
    }
    __syncthreads();

    float vprev = 0.f;   // persists in tid<16 threads
    if (tid < 16) {
        float s_u = red[tid] * (1.0f / (float)N_CAP);
        float sq = s_u * s_u;
        sq += __shfl_xor_sync(0x0000ffffu, sq, 1, 16);
        sq += __shfl_xor_sync(0x0000ffffu, sq, 2, 16);
        sq += __shfl_xor_sync(0x0000ffffu, sq, 4, 16);
        sq += __shfl_xor_sync(0x0000ffffu, sq, 8, 16);
        float scale = sq / ((1.0f + sq) * sqrtf(sq + 1e-9f));
        vprev = scale * s_u;                  // v0
        w_s[tid] = vprev;
    }
    __syncthreads();

    #pragma unroll
    for (int it = 1; it < 3; ++it) {
        // ---- fused pass: exp(u.w) and s accumulation in one n-sweep ----
        float ls = 0.f;
        float sacc[16];
        #pragma unroll
        for (int u = 0; u < 16; ++u) sacc[u] = 0.f;

        for (int j = tid; j < NQUAD; j += 256) {
            float d0 = 0.f, d1 = 0.f, d2 = 0.f, d3 = 0.f;
            #pragma unroll
            for (int q = 0; q < 8; ++q) {
                uint4 hv = *(const uint4*)(uh + q * N_CAP + 4 * j);
                float2 wv = *(const float2*)(w_s + 2 * q);
                float2 a = __half22float2(*(__half2*)&hv.x);
                float2 bq = __half22float2(*(__half2*)&hv.y);
                float2 cq = __half22float2(*(__half2*)&hv.z);
                float2 dq = __half22float2(*(__half2*)&hv.w);
                d0 = fmaf(a.x,  wv.x, fmaf(a.y,  wv.y, d0));
                d1 = fmaf(bq.x, wv.x, fmaf(bq.y, wv.y, d1));
                d2 = fmaf(cq.x, wv.x, fmaf(cq.y, wv.y, d2));
                d3 = fmaf(dq.x, wv.x, fmaf(dq.y, wv.y, d3));
            }
            float e0 = __expf(d0), e1 = __expf(d1);
            float e2 = __expf(d2), e3 = __expf(d3);
            ls += (e0 + e1) + (e2 + e3);
            #pragma unroll
            for (int q = 0; q < 8; ++q) {
                uint4 hv = *(const uint4*)(uh + q * N_CAP + 4 * j);
                float2 a = __half22float2(*(__half2*)&hv.x);
                float2 bq = __half22float2(*(__half2*)&hv.y);
                float2 cq = __half22float2(*(__half2*)&hv.z);
                float2 dq = __half22float2(*(__half2*)&hv.w);
                sacc[2 * q] += fmaf(e0, a.x, fmaf(e1, bq.x,
                               fmaf(e2, cq.x, e3 * dq.x)));
                sacc[2 * q + 1] += fmaf(e0, a.y, fmaf(e1, bq.y,
                                   fmaf(e2, cq.y, e3 * dq.y)));
            }
        }

        float inv = 1.0f / blockReduceSum(ls, red2);

        #pragma unroll
        for (int u = 0; u < 16; ++u) {
            float v = sacc[u];
            #pragma unroll
            for (int o = 16; o > 0; o >>= 1)
                v += __shfl_xor_sync(0xffffffffu, v, o);
            if (g == 0) red[p * 16 + u] = v;
        }
        __syncthreads();

        if (tid < 16) {
            float s_u = 0.f;
            #pragma unroll
            for (int w = 0; w < 8; ++w) s_u += red[w * 16 + tid];
            s_u *= inv;
            float sq = s_u * s_u;
            sq += __shfl_xor_sync(0x0000ffffu, sq, 1, 16);
            sq += __shfl_xor_sync(0x0000ffffu, sq, 2, 16);
            sq += __shfl_xor_sync(0x0000ffffu, sq, 4, 16);
            sq += __shfl_xor_sync(0x0000ffffu, sq, 8, 16);
            float scale = sq / ((1.0f + sq) * sqrtf(sq + 1e-9f));
            float vcur = scale * s_u;
            if (it == 1) {
                w_s[tid] = vprev + vcur;      // b2 weight vector (linearity)
            } else {
                outp[((size_t)b * C_SZ + c) * U_SZ + tid] = vcur;
            }
        }
        __syncthreads();
    }
}

// ---------------------------------------------------------------------------
extern "C" void kernel_launch(void* const* d_in, const int* in_sizes, int n_in,
                              void* d_out, int out_size)
{
    const float* x = (const float*)d_in[0];
    const float* W = (const float*)d_in[1];
    if (n_in >= 2 && in_sizes[0] == C_SZ * N_CAP * DIN * U_SZ &&
        in_sizes[1] == B_SZ * N_CAP * DIN) {
        const float* t = x; x = W; W = t;
    }

    const size_t smem2 = (size_t)(8 * N_CAP + 128 + 16 + 8) * sizeof(float); // 37,472B
    cudaFuncSetAttribute(k2_route, cudaFuncAttributeMaxDynamicSharedMemorySize,
                         (int)smem2);

    for (int ch = 0; ch < B_SZ / B_CHUNK; ++ch) {
        const float* xc = x + (size_t)ch * B_CHUNK * N_CAP * DIN;
        float* oc = (float*)d_out + (size_t)ch * B_CHUNK * C_SZ * U_SZ;
        k1_uhat<<<dim3(N_CAP / 32, C_SZ, B_CHUNK / 16), 256>>>(xc, W);
        k2_route<<<dim3(C_SZ, B_CHUNK), 256, smem2>>>(oc);
    }
}

// round 5
// speedup vs baseline: 2.5181x; 2.5181x over previous
#include <cuda_runtime.h>
#include <cuda_fp16.h>
#include <cstdint>
#include <cstddef>

#define B_SZ  256
#define C_SZ  10
#define N_CAP 1152
#define DIN   8
#define U_SZ  16

// 94.4 MB fp16 scratch for u_hat, layout [b][c][p][n]  (p = u-pair 0..7).
__device__ unsigned int g_uhat_h[(size_t)B_SZ * C_SZ * 8 * N_CAP];

#define FFMA2(d, a, bb, cc) \
    asm("fma.rn.f32x2 %0, %1, %2, %3;" : "=l"(d) : "l"(a), "l"(bb), "l"(cc))
#define DUP2(d, s) \
    asm("mov.b64 %0, {%1, %1};" : "=l"(d) : "r"(s))

// ---------------------------------------------------------------------------
// K1: u_hat[b,c,n,u] = sum_i x[b,n,i] * W[c,n,i,u]  -> fp16 [b][c][p][n].
// Grid (36, 10, 8). 256 thr = 2 b-halves x 32 n x 4 u-quads.
// W slice (8i x 4u) in registers (16 f32x2); x staged in smem (12-word rows,
// conflict-free LDS.128). Per b-step: 2 LDS.128 + 8 dup(ALU) + 16 FFMA2(FMA)
// + 2 STG.32 (warp = 8 distinct 32B sectors, full utilization).
// ---------------------------------------------------------------------------
__global__ __launch_bounds__(256) void k1_uhat(const float* __restrict__ x,
                                               const float* __restrict__ W)
{
    __shared__ float xs[32 * 32 * 12];   // 48KB

    const int n0 = blockIdx.x * 32;
    const int c  = blockIdx.y;
    const int b0 = blockIdx.z * 32;

    for (int t = threadIdx.x; t < 1024; t += 256) {
        const int b = t >> 5, n = t & 31;
        const float4* g = (const float4*)(x + ((size_t)(b0 + b) * N_CAP + (n0 + n)) * DIN);
        float4 v0 = g[0], v1 = g[1];
        float* d = xs + (b * 32 + n) * 12;
        *(float4*)(d)     = v0;
        *(float4*)(d + 4) = v1;
    }

    const int uq = threadIdx.x & 3;
    const int nl = (threadIdx.x >> 2) & 31;
    const int bl = threadIdx.x >> 7;     // 0..1
    const int n  = n0 + nl;

    unsigned long long wr[16];
    {
        const ulonglong2* Wp = (const ulonglong2*)(W + ((size_t)c * N_CAP + n) * 128);
        #pragma unroll
        for (int i = 0; i < 8; ++i) {
            ulonglong2 w = Wp[i * 4 + uq];
            wr[2 * i]     = w.x;
            wr[2 * i + 1] = w.y;
        }
    }
    __syncthreads();

    // store base: [b][c][p = 2uq][n]
    unsigned int* op = g_uhat_h +
        (((size_t)(b0 + bl * 16) * C_SZ + c) * 8 + 2 * uq) * N_CAP + n;

    #pragma unroll 4
    for (int s = 0; s < 16; ++s) {
        const int b = bl * 16 + s;
        const float* xp = xs + (b * 32 + nl) * 12;
        float4 xa = *(const float4*)(xp);
        float4 xb = *(const float4*)(xp + 4);

        unsigned long long x0, x1, x2, x3, x4, x5, x6, x7;
        DUP2(x0, __float_as_uint(xa.x));  DUP2(x1, __float_as_uint(xa.y));
        DUP2(x2, __float_as_uint(xa.z));  DUP2(x3, __float_as_uint(xa.w));
        DUP2(x4, __float_as_uint(xb.x));  DUP2(x5, __float_as_uint(xb.y));
        DUP2(x6, __float_as_uint(xb.z));  DUP2(x7, __float_as_uint(xb.w));

        unsigned long long a0 = 0ull, a1 = 0ull;
        FFMA2(a0, wr[0],  x0, a0);  FFMA2(a1, wr[1],  x0, a1);
        FFMA2(a0, wr[2],  x1, a0);  FFMA2(a1, wr[3],  x1, a1);
        FFMA2(a0, wr[4],  x2, a0);  FFMA2(a1, wr[5],  x2, a1);
        FFMA2(a0, wr[6],  x3, a0);  FFMA2(a1, wr[7],  x3, a1);
        FFMA2(a0, wr[8],  x4, a0);  FFMA2(a1, wr[9],  x4, a1);
        FFMA2(a0, wr[10], x5, a0);  FFMA2(a1, wr[11], x5, a1);
        FFMA2(a0, wr[12], x6, a0);  FFMA2(a1, wr[13], x6, a1);
        FFMA2(a0, wr[14], x7, a0);  FFMA2(a1, wr[15], x7, a1);

        unsigned int l0, h0, l1, h1;
        asm("mov.b64 {%0, %1}, %2;" : "=r"(l0), "=r"(h0) : "l"(a0));
        asm("mov.b64 {%0, %1}, %2;" : "=r"(l1), "=r"(h1) : "l"(a1));
        __half2 p0 = __floats2half2_rn(__uint_as_float(l0), __uint_as_float(h0));
        __half2 p1 = __floats2half2_rn(__uint_as_float(l1), __uint_as_float(h1));
        op[0]     = *(unsigned int*)&p0;
        op[N_CAP] = *(unsigned int*)&p1;
        op += (size_t)C_SZ * 8 * N_CAP;
    }
}

// ---------------------------------------------------------------------------
__device__ __forceinline__ float blockReduceSum(float v, float* scratch)
{
    #pragma unroll
    for (int o = 16; o > 0; o >>= 1) v += __shfl_xor_sync(0xffffffffu, v, o);
    if ((threadIdx.x & 31) == 0) scratch[threadIdx.x >> 5] = v;
    __syncthreads();
    float r = 0.f;
    #pragma unroll
    for (int i = 0; i < 8; ++i) r += scratch[i];
    __syncthreads();
    return r;
}

// ---------------------------------------------------------------------------
// K2: routing per (b,c). Grid (C, B), 256 thr, 41.1KB smem (5 CTAs/SM).
//  prologue: warp p streams its u-pair row (coalesced uint4) -> smem,
//            uniform-s0 fused into the stream.
//  it=1,2:  exp-scan (thread per n: dot = u.w, e = exp, c_arr[n] = e)
//           then s-phase (warp p: LDS.128 x2, 16 FMA per 4n) + squash.
//  No b_log: pass-2 weights = v0 + v1 (softmax shift-invariance + linearity).
// ---------------------------------------------------------------------------
__global__ __launch_bounds__(256, 5) void k2_route(float* __restrict__ outp)
{
    extern __shared__ float sm[];
    unsigned int* uh = (unsigned int*)sm;     // 8 x 1152 half2-words (36.9KB)
    float* c_arr = sm + 8 * N_CAP;            // 1152
    float* red   = c_arr + N_CAP;             // 16
    float* w_s   = red + 16;                  // 16
    float* red2  = w_s + 16;                  // 8

    const int tid = threadIdx.x;
    const int c   = blockIdx.x;
    const int b   = blockIdx.y;
    const int p   = tid >> 5;
    const int g   = tid & 31;
    const unsigned int* uhp = uh + p * N_CAP;

    // ---- prologue: stream row p in, fused uniform-s0 partials ----
    {
        const uint4* src = (const uint4*)(g_uhat_h +
                            (((size_t)b * C_SZ + c) * 8 + p) * N_CAP);
        unsigned int* dst = uh + p * N_CAP;
        float sx = 0.f, sy = 0.f;
        #pragma unroll
        for (int k = 0; k < 9; ++k) {
            uint4 v = src[k * 32 + g];
            *(uint4*)(dst + k * 128 + 4 * g) = v;
            float2 a0 = __half22float2(*(__half2*)&v.x);
            float2 a1 = __half22float2(*(__half2*)&v.y);
            float2 a2 = __half22float2(*(__half2*)&v.z);
            float2 a3 = __half22float2(*(__half2*)&v.w);
            sx += (a0.x + a1.x) + (a2.x + a3.x);
            sy += (a0.y + a1.y) + (a2.y + a3.y);
        }
        #pragma unroll
        for (int o = 16; o > 0; o >>= 1) {
            sx += __shfl_xor_sync(0xffffffffu, sx, o);
            sy += __shfl_xor_sync(0xffffffffu, sy, o);
        }
        if (g == 0) { red[2 * p] = sx; red[2 * p + 1] = sy; }
    }
    __syncthreads();

    float vprev = 0.f;   // v0, persists in tid<16
    if (tid < 16) {
        float s_u = red[tid] * (1.0f / (float)N_CAP);
        float sq = s_u * s_u;
        sq += __shfl_xor_sync(0x0000ffffu, sq, 1, 16);
        sq += __shfl_xor_sync(0x0000ffffu, sq, 2, 16);
        sq += __shfl_xor_sync(0x0000ffffu, sq, 4, 16);
        sq += __shfl_xor_sync(0x0000ffffu, sq, 8, 16);
        float scale = sq / ((1.0f + sq) * sqrtf(sq + 1e-9f));
        vprev = scale * s_u;
        w_s[tid] = vprev;
    }
    __syncthreads();

    #pragma unroll
    for (int it = 1; it < 3; ++it) {
        // ---- exp-scan: thread per n (stride 256, 4.5 iters, good ILP) ----
        float o2[16];
        #pragma unroll
        for (int j = 0; j < 8; ++j) {
            float2 t = *(const float2*)(w_s + 2 * j);
            o2[2 * j] = t.x;  o2[2 * j + 1] = t.y;
        }
        float ls = 0.f;
        for (int n = tid; n < N_CAP; n += 256) {
            float dot = 0.f;
            #pragma unroll
            for (int j = 0; j < 8; ++j) {
                float2 v = __half22float2(*(const __half2*)(uh + j * N_CAP + n));
                dot = fmaf(v.x, o2[2 * j], dot);
                dot = fmaf(v.y, o2[2 * j + 1], dot);
            }
            float e = __expf(dot);
            c_arr[n] = e;
            ls += e;
        }
        float inv = 1.0f / blockReduceSum(ls, red2);  // syncs publish c_arr

        // ---- s-phase: warp p over its u-pair row, LDS.128 pairs ----
        float sx = 0.f, sy = 0.f;
        #pragma unroll
        for (int k = 0; k < 9; ++k) {
            uint4 hv = *(const uint4*)(uhp + k * 128 + 4 * g);
            float4 cv = *(const float4*)(c_arr + k * 128 + 4 * g);
            float2 v0 = __half22float2(*(__half2*)&hv.x);
            float2 v1 = __half22float2(*(__half2*)&hv.y);
            float2 v2 = __half22float2(*(__half2*)&hv.z);
            float2 v3 = __half22float2(*(__half2*)&hv.w);
            sx = fmaf(cv.x, v0.x, sx);  sy = fmaf(cv.x, v0.y, sy);
            sx = fmaf(cv.y, v1.x, sx);  sy = fmaf(cv.y, v1.y, sy);
            sx = fmaf(cv.z, v2.x, sx);  sy = fmaf(cv.z, v2.y, sy);
            sx = fmaf(cv.w, v3.x, sx);  sy = fmaf(cv.w, v3.y, sy);
        }
        #pragma unroll
        for (int o = 16; o > 0; o >>= 1) {
            sx += __shfl_xor_sync(0xffffffffu, sx, o);
            sy += __shfl_xor_sync(0xffffffffu, sy, o);
        }
        if (g == 0) { red[2 * p] = sx; red[2 * p + 1] = sy; }
        __syncthreads();

        // ---- squash ----
        if (tid < 16) {
            float s_u = red[tid] * inv;
            float sq = s_u * s_u;
            sq += __shfl_xor_sync(0x0000ffffu, sq, 1, 16);
            sq += __shfl_xor_sync(0x0000ffffu, sq, 2, 16);
            sq += __shfl_xor_sync(0x0000ffffu, sq, 4, 16);
            sq += __shfl_xor_sync(0x0000ffffu, sq, 8, 16);
            float scale = sq / ((1.0f + sq) * sqrtf(sq + 1e-9f));
            float vcur = scale * s_u;
            if (it == 1) {
                w_s[tid] = vprev + vcur;   // b2 weights via linearity
            } else {
                outp[((size_t)b * C_SZ + c) * U_SZ + tid] = vcur;
            }
        }
        __syncthreads();
    }
}

// ---------------------------------------------------------------------------
extern "C" void kernel_launch(void* const* d_in, const int* in_sizes, int n_in,
                              void* d_out, int out_size)
{
    const float* x = (const float*)d_in[0];
    const float* W = (const float*)d_in[1];
    if (n_in >= 2 && in_sizes[0] == C_SZ * N_CAP * DIN * U_SZ &&
        in_sizes[1] == B_SZ * N_CAP * DIN) {
        const float* t = x; x = W; W = t;
    }

    const size_t smem2 =
        (size_t)(8 * N_CAP + N_CAP + 16 + 16 + 8) * sizeof(float); // 41,120B
    cudaFuncSetAttribute(k2_route, cudaFuncAttributeMaxDynamicSharedMemorySize,
                         (int)smem2);

    k1_uhat<<<dim3(N_CAP / 32, C_SZ, B_SZ / 32), 256>>>(x, W);
    k2_route<<<dim3(C_SZ, B_SZ), 256, smem2>>>((float*)d_out);
}